// round 15
// baseline (speedup 1.0000x reference)
#include <cuda_runtime.h>
#include <cuda_fp16.h>
#include <math_constants.h>
#include <cstdint>

#define N_NODES 50000
#define E_EDGES 800000
#define HEADS 4
#define IN_DIM 256
#define HC 256
#define NEG_SLOPE 0.2f

// ---------------- device scratch ----------------
__device__ __half g_hh[N_NODES * HC];        // x @ W in fp16 (25.6 MB)
__device__ __half g_wth[IN_DIM * HC];        // W transposed + fp16: [n][k]
__device__ float g_asrc[N_NODES * HEADS];
__device__ float g_adst[N_NODES * HEADS];
__device__ int   g_deg[N_NODES];
__device__ int   g_rowstart[N_NODES + 1];
__device__ int   g_cursor[N_NODES];
__device__ int   g_csr[E_EDGES];
__device__ unsigned int g_hi_or;             // monotone OR accumulator (idempotent across replays)
#define SCAN_BLK 1024
#define NSCAN ((N_NODES + SCAN_BLK - 1) / SCAN_BLK)   // 49
__device__ int   g_bsum[NSCAN];
__device__ int   g_scan_ready;               // phase-1 publish counter (reset per call)
__device__ int   g_fill_ready;               // phase-2 publish counter (reset per call)

// ---------------- host-side stream/event fork ----------------
struct StreamInit {
    cudaStream_t s2;
    cudaEvent_t  e1, e2, e3;
    StreamInit() {
        cudaStreamCreateWithFlags(&s2, cudaStreamNonBlocking);
        cudaEventCreateWithFlags(&e1, cudaEventDisableTiming);
        cudaEventCreateWithFlags(&e2, cudaEventDisableTiming);
        cudaEventCreateWithFlags(&e3, cudaEventDisableTiming);
    }
};
static StreamInit g_si;

// ---------------- edge decode helpers (direct from edge_index) ----------------
__device__ __forceinline__ void load_ei4(const void* ei, int base, int e, int is64,
                                         int* v) {
    if (is64) {
        const longlong2* p = (const longlong2*)((const long long*)ei + base + e);
        longlong2 a = p[0], b = p[1];
        v[0] = (int)a.x; v[1] = (int)a.y; v[2] = (int)b.x; v[3] = (int)b.y;
    } else {
        int4 a = *(const int4*)((const int*)ei + base + e);
        v[0] = a.x; v[1] = a.y; v[2] = a.z; v[3] = a.w;
    }
}

// ---------------- zero degrees + dtype detection + counter resets ----------------
__global__ void zero_deg_detect_kernel(const unsigned int* __restrict__ w) {
    int i = blockIdx.x * blockDim.x + threadIdx.x;
    if (i == 0) { g_scan_ready = 0; g_fill_ready = 0; }
    if (i < N_NODES) g_deg[i] = 0;
    if (i < 8192) {
        unsigned int v = w[2 * i + 1];
        #pragma unroll
        for (int off = 16; off; off >>= 1)
            v |= __shfl_xor_sync(0xffffffffu, v, off);
        if ((threadIdx.x & 31) == 0 && v) atomicOr(&g_hi_or, v);
    }
}

// ---------------- degree histogram straight from edge_index (x4) ----------------
__global__ void hist_kernel(const void* __restrict__ ei) {
    int e4 = blockIdx.x * blockDim.x + threadIdx.x;
    if (e4 >= E_EDGES / 4) return;
    const int e = e4 * 4;
    const int is64 = (g_hi_or == 0u);
    int d[4];
    load_ei4(ei, E_EDGES, e, is64, d);
    #pragma unroll
    for (int j = 0; j < 4; j++) atomicAdd(&g_deg[d[j]], 1);
}

// ---------------- W transpose + fp16 convert ----------------
__global__ void transpose_w_kernel(const float* __restrict__ W) {
    __shared__ float t[32][33];
    const int bx = blockIdx.x * 32, by = blockIdx.y * 32;
    #pragma unroll
    for (int i = 0; i < 4; i++)
        t[threadIdx.y + i * 8][threadIdx.x] = W[(by + threadIdx.y + i * 8) * HC + bx + threadIdx.x];
    __syncthreads();
    #pragma unroll
    for (int i = 0; i < 4; i++)
        g_wth[(bx + threadIdx.y + i * 8) * IN_DIM + by + threadIdx.x] =
            __float2half_rn(t[threadIdx.x][threadIdx.y + i * 8]);
}

// ---------------- FP16 GEMM 128x128, BK=32: A = LDG fp32 + inline convert, B = cp.async ----------------
#define GBM 128
#define GBN 128
#define GBK 32
#define STAGES 4
#define STAGE_BYTES 16384
#define GEMM_SMEM (STAGES * STAGE_BYTES)

__device__ __forceinline__ void ldsm_x4(uint32_t addr, uint32_t& r0, uint32_t& r1,
                                        uint32_t& r2, uint32_t& r3) {
    asm volatile("ldmatrix.sync.aligned.m8n8.x4.shared.b16 {%0,%1,%2,%3}, [%4];"
                 : "=r"(r0), "=r"(r1), "=r"(r2), "=r"(r3) : "r"(addr));
}

__device__ __forceinline__ void mma_f16(float4& d, const uint32_t* a, const uint32_t* b) {
    asm volatile(
        "mma.sync.aligned.m16n8k16.row.col.f32.f16.f16.f32 "
        "{%0,%1,%2,%3}, {%4,%5,%6,%7}, {%8,%9}, {%0,%1,%2,%3};\n"
        : "+f"(d.x), "+f"(d.y), "+f"(d.z), "+f"(d.w)
        : "r"(a[0]), "r"(a[1]), "r"(a[2]), "r"(a[3]),
          "r"(b[0]), "r"(b[1]));
}

__device__ __forceinline__ void cp_async16(uint32_t dst, const void* src) {
    asm volatile("cp.async.cg.shared.global [%0], [%1], 16;" :: "r"(dst), "l"(src));
}
__device__ __forceinline__ void cp_commit() {
    asm volatile("cp.async.commit_group;" ::: "memory");
}
#define CP_WAIT2() asm volatile("cp.async.wait_group 2;" ::: "memory")

__global__ __launch_bounds__(256, 2) void hgemm_kernel(
    const float* __restrict__ x,
    const float* __restrict__ att_src, const float* __restrict__ att_dst) {
    extern __shared__ __align__(16) char smem[];

    const int tid  = threadIdx.x;
    const int w    = tid >> 5;
    const int lane = tid & 31;
    const int gid  = lane >> 2;
    const int tig  = lane & 3;
    const int wm   = w & 3;
    const int wn   = w >> 2;
    const int rowblk = blockIdx.y * GBM;
    const int col0   = blockIdx.x * GBN;

    float4 acc[2][8];
    #pragma unroll
    for (int i = 0; i < 2; i++)
        #pragma unroll
        for (int j = 0; j < 8; j++) acc[i][j] = make_float4(0.f, 0.f, 0.f, 0.f);

    const uint32_t sbase = (uint32_t)__cvta_generic_to_shared(smem);

    const int c_a  = tid;
    auto dst_off = [&](int c) {
        int row = c >> 2, kc = c & 3;
        return (uint32_t)(row * 64 + (((kc) ^ ((row >> 1) & 3)) << 4));
    };
    const uint32_t dA0 = dst_off(c_a), dA1 = dst_off(c_a + 256);
    int arow0 = rowblk + (c_a >> 2);         if (arow0 > N_NODES - 1) arow0 = N_NODES - 1;
    int arow1 = rowblk + ((c_a + 256) >> 2); if (arow1 > N_NODES - 1) arow1 = N_NODES - 1;
    const int akc0 = (c_a & 3) * 8, akc1 = ((c_a + 256) & 3) * 8;
    const int brow0 = col0 + (c_a >> 2);
    const int brow1 = col0 + ((c_a + 256) >> 2);

    float4 ar0a, ar0b, ar1a, ar1b;
    auto ldgA = [&](int it) {
        const int k0 = it * GBK;
        const float* p0 = &x[(size_t)arow0 * IN_DIM + k0 + akc0];
        const float* p1 = &x[(size_t)arow1 * IN_DIM + k0 + akc1];
        ar0a = *(const float4*)p0;
        ar0b = *(const float4*)(p0 + 4);
        ar1a = *(const float4*)p1;
        ar1b = *(const float4*)(p1 + 4);
    };
    auto stsA = [&](int it) {
        char* sb = smem + (it & 3) * STAGE_BYTES;
        __align__(16) __half2 h0[4], h1[4];
        h0[0] = __floats2half2_rn(ar0a.x, ar0a.y);
        h0[1] = __floats2half2_rn(ar0a.z, ar0a.w);
        h0[2] = __floats2half2_rn(ar0b.x, ar0b.y);
        h0[3] = __floats2half2_rn(ar0b.z, ar0b.w);
        h1[0] = __floats2half2_rn(ar1a.x, ar1a.y);
        h1[1] = __floats2half2_rn(ar1a.z, ar1a.w);
        h1[2] = __floats2half2_rn(ar1b.x, ar1b.y);
        h1[3] = __floats2half2_rn(ar1b.z, ar1b.w);
        *(uint4*)(sb + dA0) = *(const uint4*)h0;
        *(uint4*)(sb + dA1) = *(const uint4*)h1;
    };
    auto issueB = [&](int it) {
        const uint32_t sb = sbase + (uint32_t)((it & 3) * STAGE_BYTES) + 8192;
        const int k0 = it * GBK;
        cp_async16(sb + dA0, &g_wth[(size_t)brow0 * IN_DIM + k0 + akc0]);
        cp_async16(sb + dA1, &g_wth[(size_t)brow1 * IN_DIM + k0 + akc1]);
    };

    const int lr  = lane & 15;
    const int csl = lane >> 4;
    const int q2  = (lr >> 1) & 3;
    const uint32_t loff0 = lr * 64 + (((0 + csl) ^ q2) << 4);
    const uint32_t loff1 = lr * 64 + (((2 + csl) ^ q2) << 4);

    auto compute = [&](int it) {
        const uint32_t Ab = sbase + (uint32_t)((it & 3) * STAGE_BYTES);
        const uint32_t Bb = Ab + 8192;
        #pragma unroll
        for (int kbi = 0; kbi < 2; kbi++) {
            const uint32_t lo = kbi ? loff1 : loff0;
            uint32_t afr[2][4], bfr[8][2];
            #pragma unroll
            for (int mt = 0; mt < 2; mt++) {
                uint32_t addr = Ab + (uint32_t)((wm * 32 + mt * 16) * 64) + lo;
                ldsm_x4(addr, afr[mt][0], afr[mt][1], afr[mt][2], afr[mt][3]);
            }
            #pragma unroll
            for (int ntp = 0; ntp < 4; ntp++) {
                uint32_t addr = Bb + (uint32_t)((wn * 64 + ntp * 16) * 64) + lo;
                ldsm_x4(addr, bfr[2 * ntp][0], bfr[2 * ntp + 1][0],
                              bfr[2 * ntp][1], bfr[2 * ntp + 1][1]);
            }
            #pragma unroll
            for (int mt = 0; mt < 2; mt++)
                #pragma unroll
                for (int nt = 0; nt < 8; nt++)
                    mma_f16(acc[mt][nt], afr[mt], bfr[nt]);
        }
    };

    const int NIT = IN_DIM / GBK;   // 8
    ldgA(0);
    #pragma unroll
    for (int s = 0; s < STAGES - 1; s++) { issueB(s); cp_commit(); }

    for (int it = 0; it < NIT; ++it) {
        CP_WAIT2();
        __syncthreads();
        stsA(it);
        if (it + 1 < NIT) ldgA(it + 1);
        if (it + STAGES - 1 < NIT) issueB(it + STAGES - 1);
        cp_commit();
        __syncthreads();
        compute(it);
    }

    // epilogue: store h (fp16) + fused attention dots (warp cols = one head)
    const int head = blockIdx.x * 2 + wn;
    float2 avs[8], avd[8];
    #pragma unroll
    for (int nt = 0; nt < 8; nt++) {
        int c = col0 + wn * 64 + nt * 8 + tig * 2;
        avs[nt] = *(const float2*)&att_src[c];
        avd[nt] = *(const float2*)&att_dst[c];
    }

    #pragma unroll
    for (int mt = 0; mt < 2; mt++) {
        int row0 = rowblk + wm * 32 + mt * 16 + gid;
        int row1 = row0 + 8;
        float s0 = 0.f, s1 = 0.f, t0 = 0.f, t1 = 0.f;
        #pragma unroll
        for (int nt = 0; nt < 8; nt++) {
            float4 d = acc[mt][nt];
            int col = col0 + wn * 64 + nt * 8 + tig * 2;
            if (row0 < N_NODES)
                *(__half2*)&g_hh[(size_t)row0 * HC + col] = __floats2half2_rn(d.x, d.y);
            if (row1 < N_NODES)
                *(__half2*)&g_hh[(size_t)row1 * HC + col] = __floats2half2_rn(d.z, d.w);
            s0 += d.x * avs[nt].x + d.y * avs[nt].y;
            s1 += d.z * avs[nt].x + d.w * avs[nt].y;
            t0 += d.x * avd[nt].x + d.y * avd[nt].y;
            t1 += d.z * avd[nt].x + d.w * avd[nt].y;
        }
        #pragma unroll
        for (int off = 1; off <= 2; off <<= 1) {
            s0 += __shfl_xor_sync(0xffffffffu, s0, off);
            s1 += __shfl_xor_sync(0xffffffffu, s1, off);
            t0 += __shfl_xor_sync(0xffffffffu, t0, off);
            t1 += __shfl_xor_sync(0xffffffffu, t1, off);
        }
        if (tig == 0) {
            if (row0 < N_NODES) { g_asrc[row0 * HEADS + head] = s0; g_adst[row0 * HEADS + head] = t0; }
            if (row1 < N_NODES) { g_asrc[row1 * HEADS + head] = s1; g_adst[row1 * HEADS + head] = t1; }
        }
    }
}

// ---------------- scan + fill fused (49 resident blocks, two spin barriers) ----------------
__global__ void scan_fill_kernel(const void* __restrict__ ei) {
    __shared__ int wsums[32];
    __shared__ int s_off;
    const int tid = threadIdx.x, wid = tid >> 5, lane = tid & 31;
    const int bid = blockIdx.x;
    int i = bid * SCAN_BLK + tid;
    int v = (i < N_NODES) ? g_deg[i] : 0;
    int incl = v;
    #pragma unroll
    for (int off = 1; off < 32; off <<= 1) {
        int t = __shfl_up_sync(0xffffffffu, incl, off);
        if (lane >= off) incl += t;
    }
    if (lane == 31) wsums[wid] = incl;
    __syncthreads();
    if (wid == 0) {
        int wv = wsums[lane];
        #pragma unroll
        for (int off = 1; off < 32; off <<= 1) {
            int t = __shfl_up_sync(0xffffffffu, wv, off);
            if (lane >= off) wv += t;
        }
        wsums[lane] = wv;
    }
    __syncthreads();

    // barrier 1: publish block sums
    if (tid == 0) {
        g_bsum[bid] = wsums[31];
        __threadfence();
        atomicAdd(&g_scan_ready, 1);
        while (*(volatile int*)&g_scan_ready < NSCAN) { }
    }
    __syncthreads();

    if (wid == 0) {
        int ov = 0;
        if (lane < bid) ov = g_bsum[lane];
        if (lane + 32 < bid) ov += g_bsum[lane + 32];
        #pragma unroll
        for (int off = 16; off; off >>= 1) ov += __shfl_xor_sync(0xffffffffu, ov, off);
        if (lane == 0) s_off = ov;
    }
    __syncthreads();

    if (i < N_NODES) {
        int start = s_off + ((wid > 0) ? wsums[wid - 1] : 0) + incl - v;
        g_rowstart[i] = start;
        g_cursor[i]   = start;
    }
    if (bid == NSCAN - 1 && tid == 0)
        g_rowstart[N_NODES] = s_off + wsums[31];

    // barrier 2: all cursors globally visible, then fill
    __threadfence();
    __syncthreads();
    if (tid == 0) {
        atomicAdd(&g_fill_ready, 1);
        while (*(volatile int*)&g_fill_ready < NSCAN) { }
    }
    __syncthreads();
    __threadfence();

    const int is64 = (g_hi_or == 0u);
    const int NT = NSCAN * SCAN_BLK;
    for (int e4 = bid * SCAN_BLK + tid; e4 < E_EDGES / 4; e4 += NT) {
        const int e = e4 * 4;
        int s[4], d[4];
        load_ei4(ei, 0, e, is64, s);
        load_ei4(ei, E_EDGES, e, is64, d);
        #pragma unroll
        for (int j = 0; j < 4; j++)
            g_csr[atomicAdd(&g_cursor[d[j]], 1)] = s[j];
    }
}

// ---------------- fused softmax + gather + bias + relu (fp16 features) ----------------
#define CAP 96
__device__ __forceinline__ void h8_accum(const __half* p, float a, float* acc) {
    uint4 v = *(const uint4*)p;
    float2 f0 = __half22float2(*(const __half2*)&v.x);
    float2 f1 = __half22float2(*(const __half2*)&v.y);
    float2 f2 = __half22float2(*(const __half2*)&v.z);
    float2 f3 = __half22float2(*(const __half2*)&v.w);
    acc[0] += a * f0.x; acc[1] += a * f0.y;
    acc[2] += a * f1.x; acc[3] += a * f1.y;
    acc[4] += a * f2.x; acc[5] += a * f2.y;
    acc[6] += a * f3.x; acc[7] += a * f3.y;
}

__global__ __launch_bounds__(256) void gat_node_kernel(const float* __restrict__ bias,
                                                       float* __restrict__ out) {
    __shared__ float s_lg[8][CAP][4];
    __shared__ int   s_src[8][CAP];

    const int w    = threadIdx.x >> 5;
    const int lane = threadIdx.x & 31;
    const int node = (blockIdx.x * blockDim.x + threadIdx.x) >> 5;
    if (node >= N_NODES) return;
    const int n   = node;
    const int rs  = g_rowstart[n];
    const int deg = g_rowstart[n + 1] - rs;
    const int tot = deg + 1;

    float4 ad4 = *(const float4*)&g_adst[n * HEADS];
    float ad[4] = {ad4.x, ad4.y, ad4.z, ad4.w};
    const int myh = lane >> 3;

    float acc[8] = {0.f, 0.f, 0.f, 0.f, 0.f, 0.f, 0.f, 0.f};

    if (tot <= CAP) {
        float m[4] = {-CUDART_INF_F, -CUDART_INF_F, -CUDART_INF_F, -CUDART_INF_F};
        for (int i = lane; i < tot; i += 32) {
            int src = (i < deg) ? g_csr[rs + i] : n;
            s_src[w][i] = src;
            float4 a4 = *(const float4*)&g_asrc[src * HEADS];
            float lg[4] = {a4.x + ad[0], a4.y + ad[1], a4.z + ad[2], a4.w + ad[3]};
            #pragma unroll
            for (int h = 0; h < 4; h++) {
                lg[h] = lg[h] >= 0.f ? lg[h] : NEG_SLOPE * lg[h];
                m[h] = fmaxf(m[h], lg[h]);
            }
            *(float4*)&s_lg[w][i][0] = make_float4(lg[0], lg[1], lg[2], lg[3]);
        }
        #pragma unroll
        for (int off = 16; off; off >>= 1)
            #pragma unroll
            for (int h = 0; h < 4; h++)
                m[h] = fmaxf(m[h], __shfl_xor_sync(0xffffffffu, m[h], off));

        float s[4] = {0.f, 0.f, 0.f, 0.f};
        for (int i = lane; i < tot; i += 32) {
            float4 L = *(const float4*)&s_lg[w][i][0];
            float e0 = __expf(L.x - m[0]);
            float e1 = __expf(L.y - m[1]);
            float e2 = __expf(L.z - m[2]);
            float e3 = __expf(L.w - m[3]);
            s[0] += e0; s[1] += e1; s[2] += e2; s[3] += e3;
            *(float4*)&s_lg[w][i][0] = make_float4(e0, e1, e2, e3);
        }
        #pragma unroll
        for (int off = 16; off; off >>= 1)
            #pragma unroll
            for (int h = 0; h < 4; h++)
                s[h] += __shfl_xor_sync(0xffffffffu, s[h], off);

        const float inv = 1.f / (s[myh] + 1e-16f);
        __syncwarp();

        int i = 0;
        for (; i + 4 <= tot; i += 4) {
            int   sA = s_src[w][i],     sB = s_src[w][i + 1];
            int   sC = s_src[w][i + 2], sD = s_src[w][i + 3];
            float aA = s_lg[w][i][myh] * inv,     aB = s_lg[w][i + 1][myh] * inv;
            float aC = s_lg[w][i + 2][myh] * inv, aD = s_lg[w][i + 3][myh] * inv;
            h8_accum(&g_hh[(size_t)sA * HC + lane * 8], aA, acc);
            h8_accum(&g_hh[(size_t)sB * HC + lane * 8], aB, acc);
            h8_accum(&g_hh[(size_t)sC * HC + lane * 8], aC, acc);
            h8_accum(&g_hh[(size_t)sD * HC + lane * 8], aD, acc);
        }
        for (; i < tot; i++) {
            int   s0 = s_src[w][i];
            float a0 = s_lg[w][i][myh] * inv;
            h8_accum(&g_hh[(size_t)s0 * HC + lane * 8], a0, acc);
        }
    } else {
        float m[4] = {-CUDART_INF_F, -CUDART_INF_F, -CUDART_INF_F, -CUDART_INF_F};
        for (int i = lane; i < tot; i += 32) {
            int src = (i < deg) ? g_csr[rs + i] : n;
            float4 a4 = *(const float4*)&g_asrc[src * HEADS];
            float lg[4] = {a4.x + ad[0], a4.y + ad[1], a4.z + ad[2], a4.w + ad[3]};
            #pragma unroll
            for (int h = 0; h < 4; h++) {
                float v = lg[h] >= 0.f ? lg[h] : NEG_SLOPE * lg[h];
                m[h] = fmaxf(m[h], v);
            }
        }
        #pragma unroll
        for (int off = 16; off; off >>= 1)
            #pragma unroll
            for (int h = 0; h < 4; h++)
                m[h] = fmaxf(m[h], __shfl_xor_sync(0xffffffffu, m[h], off));

        float s[4] = {0.f, 0.f, 0.f, 0.f};
        for (int i = lane; i < tot; i += 32) {
            int src = (i < deg) ? g_csr[rs + i] : n;
            float4 a4 = *(const float4*)&g_asrc[src * HEADS];
            float lg[4] = {a4.x + ad[0], a4.y + ad[1], a4.z + ad[2], a4.w + ad[3]};
            #pragma unroll
            for (int h = 0; h < 4; h++) {
                float v = lg[h] >= 0.f ? lg[h] : NEG_SLOPE * lg[h];
                s[h] += __expf(v - m[h]);
            }
        }
        #pragma unroll
        for (int off = 16; off; off >>= 1)
            #pragma unroll
            for (int h = 0; h < 4; h++)
                s[h] += __shfl_xor_sync(0xffffffffu, s[h], off);

        const float mh  = m[myh];
        const float inv = 1.f / (s[myh] + 1e-16f);
        const float adh = ad[myh];
        for (int i = 0; i < tot; i++) {
            int src = (i < deg) ? g_csr[rs + i] : n;
            float av = g_asrc[src * HEADS + myh];
            float lg = av + adh;
            lg = lg >= 0.f ? lg : NEG_SLOPE * lg;
            float alpha = __expf(lg - mh) * inv;
            h8_accum(&g_hh[(size_t)src * HC + lane * 8], alpha, acc);
        }
    }

    float4 b0 = ((const float4*)bias)[lane * 2];
    float4 b1 = ((const float4*)bias)[lane * 2 + 1];
    float4 o0, o1;
    o0.x = fmaxf(acc[0] + b0.x, 0.f); o0.y = fmaxf(acc[1] + b0.y, 0.f);
    o0.z = fmaxf(acc[2] + b0.z, 0.f); o0.w = fmaxf(acc[3] + b0.w, 0.f);
    o1.x = fmaxf(acc[4] + b1.x, 0.f); o1.y = fmaxf(acc[5] + b1.y, 0.f);
    o1.z = fmaxf(acc[6] + b1.z, 0.f); o1.w = fmaxf(acc[7] + b1.w, 0.f);
    *(float4*)&out[(size_t)n * HC + lane * 8]     = o0;
    *(float4*)&out[(size_t)n * HC + lane * 8 + 4] = o1;
}

// ---------------- launch ----------------
extern "C" void kernel_launch(void* const* d_in, const int* in_sizes, int n_in,
                              void* d_out, int out_size) {
    const float* x       = (const float*)d_in[0];
    const void*  ei      = d_in[1];
    const float* W       = (const float*)d_in[2];
    const float* att_src = (const float*)d_in[3];
    const float* att_dst = (const float*)d_in[4];
    const float* bias    = (const float*)d_in[5];
    float*       out     = (float*)d_out;

    cudaFuncSetAttribute(hgemm_kernel,
                         cudaFuncAttributeMaxDynamicSharedMemorySize, GEMM_SMEM);

    // fork
    cudaEventRecord(g_si.e1, 0);
    cudaStreamWaitEvent(g_si.s2, g_si.e1, 0);

    // side stream: W transpose first (GEMM waits on e3), then CSR build chain
    dim3 tg(8, 8);
    transpose_w_kernel<<<tg, dim3(32, 8), 0, g_si.s2>>>(W);
    cudaEventRecord(g_si.e3, g_si.s2);
    zero_deg_detect_kernel<<<(N_NODES + 255) / 256, 256, 0, g_si.s2>>>((const unsigned int*)ei);
    hist_kernel<<<(E_EDGES / 4 + 255) / 256, 256, 0, g_si.s2>>>(ei);
    scan_fill_kernel<<<NSCAN, SCAN_BLK, 0, g_si.s2>>>(ei);
    cudaEventRecord(g_si.e2, g_si.s2);

    // main stream: GEMM directly on fp32 x (waits on transpose)
    cudaStreamWaitEvent(0, g_si.e3, 0);
    dim3 gg(HC / GBN, (N_NODES + GBM - 1) / GBM);   // (2, 391)
    hgemm_kernel<<<gg, 256, GEMM_SMEM>>>(x, att_src, att_dst);

    // join: gather needs both chains
    cudaStreamWaitEvent(0, g_si.e2, 0);
    gat_node_kernel<<<(N_NODES + 7) / 8, 256>>>(bias, out);
}

// round 16
// speedup vs baseline: 1.0824x; 1.0824x over previous
#include <cuda_runtime.h>
#include <cuda_fp16.h>
#include <math_constants.h>
#include <cstdint>

#define N_NODES 50000
#define E_EDGES 800000
#define HEADS 4
#define IN_DIM 256
#define HC 256
#define NEG_SLOPE 0.2f

// ---------------- device scratch ----------------
__device__ __half g_hh[N_NODES * HC];        // x @ W in fp16 (25.6 MB)
__device__ __half g_wth[IN_DIM * HC];        // W transposed + fp16: [n][k]
__device__ float g_asrc[N_NODES * HEADS];
__device__ float g_adst[N_NODES * HEADS];
__device__ int   g_deg[N_NODES];
__device__ int   g_rowstart[N_NODES + 1];
__device__ int   g_cursor[N_NODES];
__device__ int   g_csr[E_EDGES];
__device__ unsigned int g_hi_or;             // monotone OR accumulator (idempotent across replays)
#define SCAN_BLK 1024
#define NSCAN ((N_NODES + SCAN_BLK - 1) / SCAN_BLK)   // 49
__device__ int   g_bsum[NSCAN];
__device__ int   g_scan_ready;               // publish counter, reset each call

// ---------------- host-side stream/event fork ----------------
struct StreamInit {
    cudaStream_t s2;
    cudaEvent_t  e1, e2, e3;
    StreamInit() {
        cudaStreamCreateWithFlags(&s2, cudaStreamNonBlocking);
        cudaEventCreateWithFlags(&e1, cudaEventDisableTiming);
        cudaEventCreateWithFlags(&e2, cudaEventDisableTiming);
        cudaEventCreateWithFlags(&e3, cudaEventDisableTiming);
    }
};
static StreamInit g_si;

// ---------------- edge decode helpers (direct from edge_index) ----------------
__device__ __forceinline__ void load_ei4(const void* ei, int base, int e, int is64,
                                         int* v) {
    if (is64) {
        const longlong2* p = (const longlong2*)((const long long*)ei + base + e);
        longlong2 a = p[0], b = p[1];
        v[0] = (int)a.x; v[1] = (int)a.y; v[2] = (int)b.x; v[3] = (int)b.y;
    } else {
        int4 a = *(const int4*)((const int*)ei + base + e);
        v[0] = a.x; v[1] = a.y; v[2] = a.z; v[3] = a.w;
    }
}

// ---------------- zero degrees + fused dtype detection + scan-counter reset ----------------
__global__ void zero_deg_detect_kernel(const unsigned int* __restrict__ w) {
    int i = blockIdx.x * blockDim.x + threadIdx.x;
    if (i == 0) g_scan_ready = 0;
    if (i < N_NODES) g_deg[i] = 0;
    if (i < 8192) {
        unsigned int v = w[2 * i + 1];
        #pragma unroll
        for (int off = 16; off; off >>= 1)
            v |= __shfl_xor_sync(0xffffffffu, v, off);
        if ((threadIdx.x & 31) == 0 && v) atomicOr(&g_hi_or, v);
    }
}

// ---------------- degree histogram straight from edge_index (x4) ----------------
__global__ void hist_kernel(const void* __restrict__ ei) {
    int e4 = blockIdx.x * blockDim.x + threadIdx.x;
    if (e4 >= E_EDGES / 4) return;
    const int e = e4 * 4;
    const int is64 = (g_hi_or == 0u);
    int d[4];
    load_ei4(ei, E_EDGES, e, is64, d);
    #pragma unroll
    for (int j = 0; j < 4; j++) atomicAdd(&g_deg[d[j]], 1);
}

// ---------------- W transpose + fp16 convert ----------------
__global__ void transpose_w_kernel(const float* __restrict__ W) {
    __shared__ float t[32][33];
    const int bx = blockIdx.x * 32, by = blockIdx.y * 32;
    #pragma unroll
    for (int i = 0; i < 4; i++)
        t[threadIdx.y + i * 8][threadIdx.x] = W[(by + threadIdx.y + i * 8) * HC + bx + threadIdx.x];
    __syncthreads();
    #pragma unroll
    for (int i = 0; i < 4; i++)
        g_wth[(bx + threadIdx.y + i * 8) * IN_DIM + by + threadIdx.x] =
            __float2half_rn(t[threadIdx.x][threadIdx.y + i * 8]);
}

// ---------------- FP16 GEMM 128x128, BK=32: A = LDG fp32 + inline convert, B = cp.async ----------------
#define GBM 128
#define GBN 128
#define GBK 32
#define STAGES 4
#define STAGE_BYTES 16384
#define GEMM_SMEM (STAGES * STAGE_BYTES)

__device__ __forceinline__ void ldsm_x4(uint32_t addr, uint32_t& r0, uint32_t& r1,
                                        uint32_t& r2, uint32_t& r3) {
    asm volatile("ldmatrix.sync.aligned.m8n8.x4.shared.b16 {%0,%1,%2,%3}, [%4];"
                 : "=r"(r0), "=r"(r1), "=r"(r2), "=r"(r3) : "r"(addr));
}

__device__ __forceinline__ void mma_f16(float4& d, const uint32_t* a, const uint32_t* b) {
    asm volatile(
        "mma.sync.aligned.m16n8k16.row.col.f32.f16.f16.f32 "
        "{%0,%1,%2,%3}, {%4,%5,%6,%7}, {%8,%9}, {%0,%1,%2,%3};\n"
        : "+f"(d.x), "+f"(d.y), "+f"(d.z), "+f"(d.w)
        : "r"(a[0]), "r"(a[1]), "r"(a[2]), "r"(a[3]),
          "r"(b[0]), "r"(b[1]));
}

__device__ __forceinline__ void cp_async16(uint32_t dst, const void* src) {
    asm volatile("cp.async.cg.shared.global [%0], [%1], 16;" :: "r"(dst), "l"(src));
}
__device__ __forceinline__ void cp_commit() {
    asm volatile("cp.async.commit_group;" ::: "memory");
}
#define CP_WAIT2() asm volatile("cp.async.wait_group 2;" ::: "memory")

__global__ __launch_bounds__(256, 2) void hgemm_kernel(
    const float* __restrict__ x,
    const float* __restrict__ att_src, const float* __restrict__ att_dst) {
    extern __shared__ __align__(16) char smem[];

    const int tid  = threadIdx.x;
    const int w    = tid >> 5;
    const int lane = tid & 31;
    const int gid  = lane >> 2;
    const int tig  = lane & 3;
    const int wm   = w & 3;
    const int wn   = w >> 2;
    const int rowblk = blockIdx.y * GBM;
    const int col0   = blockIdx.x * GBN;

    float4 acc[2][8];
    #pragma unroll
    for (int i = 0; i < 2; i++)
        #pragma unroll
        for (int j = 0; j < 8; j++) acc[i][j] = make_float4(0.f, 0.f, 0.f, 0.f);

    const uint32_t sbase = (uint32_t)__cvta_generic_to_shared(smem);

    const int c_a  = tid;
    auto dst_off = [&](int c) {
        int row = c >> 2, kc = c & 3;
        return (uint32_t)(row * 64 + (((kc) ^ ((row >> 1) & 3)) << 4));
    };
    const uint32_t dA0 = dst_off(c_a), dA1 = dst_off(c_a + 256);
    int arow0 = rowblk + (c_a >> 2);         if (arow0 > N_NODES - 1) arow0 = N_NODES - 1;
    int arow1 = rowblk + ((c_a + 256) >> 2); if (arow1 > N_NODES - 1) arow1 = N_NODES - 1;
    const int akc0 = (c_a & 3) * 8, akc1 = ((c_a + 256) & 3) * 8;
    const int brow0 = col0 + (c_a >> 2);
    const int brow1 = col0 + ((c_a + 256) >> 2);

    float4 ar0a, ar0b, ar1a, ar1b;
    auto ldgA = [&](int it) {
        const int k0 = it * GBK;
        const float* p0 = &x[(size_t)arow0 * IN_DIM + k0 + akc0];
        const float* p1 = &x[(size_t)arow1 * IN_DIM + k0 + akc1];
        ar0a = *(const float4*)p0;
        ar0b = *(const float4*)(p0 + 4);
        ar1a = *(const float4*)p1;
        ar1b = *(const float4*)(p1 + 4);
    };
    auto stsA = [&](int it) {
        char* sb = smem + (it & 3) * STAGE_BYTES;
        __align__(16) __half2 h0[4], h1[4];
        h0[0] = __floats2half2_rn(ar0a.x, ar0a.y);
        h0[1] = __floats2half2_rn(ar0a.z, ar0a.w);
        h0[2] = __floats2half2_rn(ar0b.x, ar0b.y);
        h0[3] = __floats2half2_rn(ar0b.z, ar0b.w);
        h1[0] = __floats2half2_rn(ar1a.x, ar1a.y);
        h1[1] = __floats2half2_rn(ar1a.z, ar1a.w);
        h1[2] = __floats2half2_rn(ar1b.x, ar1b.y);
        h1[3] = __floats2half2_rn(ar1b.z, ar1b.w);
        *(uint4*)(sb + dA0) = *(const uint4*)h0;
        *(uint4*)(sb + dA1) = *(const uint4*)h1;
    };
    auto issueB = [&](int it) {
        const uint32_t sb = sbase + (uint32_t)((it & 3) * STAGE_BYTES) + 8192;
        const int k0 = it * GBK;
        cp_async16(sb + dA0, &g_wth[(size_t)brow0 * IN_DIM + k0 + akc0]);
        cp_async16(sb + dA1, &g_wth[(size_t)brow1 * IN_DIM + k0 + akc1]);
    };

    const int lr  = lane & 15;
    const int csl = lane >> 4;
    const int q2  = (lr >> 1) & 3;
    const uint32_t loff0 = lr * 64 + (((0 + csl) ^ q2) << 4);
    const uint32_t loff1 = lr * 64 + (((2 + csl) ^ q2) << 4);

    auto compute = [&](int it) {
        const uint32_t Ab = sbase + (uint32_t)((it & 3) * STAGE_BYTES);
        const uint32_t Bb = Ab + 8192;
        #pragma unroll
        for (int kbi = 0; kbi < 2; kbi++) {
            const uint32_t lo = kbi ? loff1 : loff0;
            uint32_t afr[2][4], bfr[8][2];
            #pragma unroll
            for (int mt = 0; mt < 2; mt++) {
                uint32_t addr = Ab + (uint32_t)((wm * 32 + mt * 16) * 64) + lo;
                ldsm_x4(addr, afr[mt][0], afr[mt][1], afr[mt][2], afr[mt][3]);
            }
            #pragma unroll
            for (int ntp = 0; ntp < 4; ntp++) {
                uint32_t addr = Bb + (uint32_t)((wn * 64 + ntp * 16) * 64) + lo;
                ldsm_x4(addr, bfr[2 * ntp][0], bfr[2 * ntp + 1][0],
                              bfr[2 * ntp][1], bfr[2 * ntp + 1][1]);
            }
            #pragma unroll
            for (int mt = 0; mt < 2; mt++)
                #pragma unroll
                for (int nt = 0; nt < 8; nt++)
                    mma_f16(acc[mt][nt], afr[mt], bfr[nt]);
        }
    };

    const int NIT = IN_DIM / GBK;   // 8
    // prologue: A regs for stage 0; B stages 0..2 in flight
    ldgA(0);
    #pragma unroll
    for (int s = 0; s < STAGES - 1; s++) { issueB(s); cp_commit(); }

    // single barrier per iteration:
    //   skew is bounded to <=1 iter by the barrier; stsA(it) writes stage it&3
    //   while the slowest warp reads stage (it-1)&3 -> disjoint. issueB(it+3)
    //   (stage (it-1)&3) is placed AFTER the barrier so every warp has finished
    //   compute(it-1) on that stage before the async write can land.
    for (int it = 0; it < NIT; ++it) {
        CP_WAIT2();                 // B(it) resident
        stsA(it);                   // A fp16 into stage it (disjoint from compute(it-1))
        if (it + 1 < NIT) ldgA(it + 1);
        __syncthreads();            // stsA visible; all warps past compute(it-1)
        if (it + STAGES - 1 < NIT) issueB(it + STAGES - 1);
        cp_commit();
        compute(it);
    }

    // epilogue: store h (fp16) + fused attention dots (warp cols = one head)
    const int head = blockIdx.x * 2 + wn;
    float2 avs[8], avd[8];
    #pragma unroll
    for (int nt = 0; nt < 8; nt++) {
        int c = col0 + wn * 64 + nt * 8 + tig * 2;
        avs[nt] = *(const float2*)&att_src[c];
        avd[nt] = *(const float2*)&att_dst[c];
    }

    #pragma unroll
    for (int mt = 0; mt < 2; mt++) {
        int row0 = rowblk + wm * 32 + mt * 16 + gid;
        int row1 = row0 + 8;
        float s0 = 0.f, s1 = 0.f, t0 = 0.f, t1 = 0.f;
        #pragma unroll
        for (int nt = 0; nt < 8; nt++) {
            float4 d = acc[mt][nt];
            int col = col0 + wn * 64 + nt * 8 + tig * 2;
            if (row0 < N_NODES)
                *(__half2*)&g_hh[(size_t)row0 * HC + col] = __floats2half2_rn(d.x, d.y);
            if (row1 < N_NODES)
                *(__half2*)&g_hh[(size_t)row1 * HC + col] = __floats2half2_rn(d.z, d.w);
            s0 += d.x * avs[nt].x + d.y * avs[nt].y;
            s1 += d.z * avs[nt].x + d.w * avs[nt].y;
            t0 += d.x * avd[nt].x + d.y * avd[nt].y;
            t1 += d.z * avd[nt].x + d.w * avd[nt].y;
        }
        #pragma unroll
        for (int off = 1; off <= 2; off <<= 1) {
            s0 += __shfl_xor_sync(0xffffffffu, s0, off);
            s1 += __shfl_xor_sync(0xffffffffu, s1, off);
            t0 += __shfl_xor_sync(0xffffffffu, t0, off);
            t1 += __shfl_xor_sync(0xffffffffu, t1, off);
        }
        if (tig == 0) {
            if (row0 < N_NODES) { g_asrc[row0 * HEADS + head] = s0; g_adst[row0 * HEADS + head] = t0; }
            if (row1 < N_NODES) { g_asrc[row1 * HEADS + head] = s1; g_adst[row1 * HEADS + head] = t1; }
        }
    }
}

// ---------------- single-kernel decoupled scan (49 blocks, all resident) ----------------
__global__ void scan_fused_kernel() {
    __shared__ int wsums[32];
    __shared__ int s_off;
    const int tid = threadIdx.x, wid = tid >> 5, lane = tid & 31;
    const int bid = blockIdx.x;
    int i = bid * SCAN_BLK + tid;
    int v = (i < N_NODES) ? g_deg[i] : 0;
    int incl = v;
    #pragma unroll
    for (int off = 1; off < 32; off <<= 1) {
        int t = __shfl_up_sync(0xffffffffu, incl, off);
        if (lane >= off) incl += t;
    }
    if (lane == 31) wsums[wid] = incl;
    __syncthreads();
    if (wid == 0) {
        int wv = wsums[lane];
        #pragma unroll
        for (int off = 1; off < 32; off <<= 1) {
            int t = __shfl_up_sync(0xffffffffu, wv, off);
            if (lane >= off) wv += t;
        }
        wsums[lane] = wv;
    }
    __syncthreads();

    if (tid == 0) {
        g_bsum[bid] = wsums[31];
        __threadfence();
        atomicAdd(&g_scan_ready, 1);
        while (*(volatile int*)&g_scan_ready < NSCAN) { }
    }
    __syncthreads();

    if (wid == 0) {
        int ov = 0;
        if (lane < bid) ov = g_bsum[lane];
        if (lane + 32 < bid) ov += g_bsum[lane + 32];
        #pragma unroll
        for (int off = 16; off; off >>= 1) ov += __shfl_xor_sync(0xffffffffu, ov, off);
        if (lane == 0) s_off = ov;
    }
    __syncthreads();

    if (i < N_NODES) {
        int start = s_off + ((wid > 0) ? wsums[wid - 1] : 0) + incl - v;
        g_rowstart[i] = start;
        g_cursor[i]   = start;
    }
    if (bid == NSCAN - 1 && tid == 0)
        g_rowstart[N_NODES] = s_off + wsums[31];
}

// ---------------- fill straight from edge_index (x4) ----------------
__global__ void fill_kernel(const void* __restrict__ ei) {
    int e4 = blockIdx.x * blockDim.x + threadIdx.x;
    if (e4 >= E_EDGES / 4) return;
    const int e = e4 * 4;
    const int is64 = (g_hi_or == 0u);
    int s[4], d[4];
    load_ei4(ei, 0, e, is64, s);
    load_ei4(ei, E_EDGES, e, is64, d);
    #pragma unroll
    for (int j = 0; j < 4; j++)
        g_csr[atomicAdd(&g_cursor[d[j]], 1)] = s[j];
}

// ---------------- fused softmax + gather + bias + relu (fp16 features) ----------------
#define CAP 96
__device__ __forceinline__ void h8_accum(const __half* p, float a, float* acc) {
    uint4 v = *(const uint4*)p;
    float2 f0 = __half22float2(*(const __half2*)&v.x);
    float2 f1 = __half22float2(*(const __half2*)&v.y);
    float2 f2 = __half22float2(*(const __half2*)&v.z);
    float2 f3 = __half22float2(*(const __half2*)&v.w);
    acc[0] += a * f0.x; acc[1] += a * f0.y;
    acc[2] += a * f1.x; acc[3] += a * f1.y;
    acc[4] += a * f2.x; acc[5] += a * f2.y;
    acc[6] += a * f3.x; acc[7] += a * f3.y;
}

__global__ __launch_bounds__(256) void gat_node_kernel(const float* __restrict__ bias,
                                                       float* __restrict__ out) {
    __shared__ float s_lg[8][CAP][4];
    __shared__ int   s_src[8][CAP];

    const int w    = threadIdx.x >> 5;
    const int lane = threadIdx.x & 31;
    const int node = (blockIdx.x * blockDim.x + threadIdx.x) >> 5;
    if (node >= N_NODES) return;
    const int n   = node;
    const int rs  = g_rowstart[n];
    const int deg = g_rowstart[n + 1] - rs;
    const int tot = deg + 1;

    float4 ad4 = *(const float4*)&g_adst[n * HEADS];
    float ad[4] = {ad4.x, ad4.y, ad4.z, ad4.w};
    const int myh = lane >> 3;

    float acc[8] = {0.f, 0.f, 0.f, 0.f, 0.f, 0.f, 0.f, 0.f};

    if (tot <= CAP) {
        float m[4] = {-CUDART_INF_F, -CUDART_INF_F, -CUDART_INF_F, -CUDART_INF_F};
        for (int i = lane; i < tot; i += 32) {
            int src = (i < deg) ? g_csr[rs + i] : n;
            s_src[w][i] = src;
            float4 a4 = *(const float4*)&g_asrc[src * HEADS];
            float lg[4] = {a4.x + ad[0], a4.y + ad[1], a4.z + ad[2], a4.w + ad[3]};
            #pragma unroll
            for (int h = 0; h < 4; h++) {
                lg[h] = lg[h] >= 0.f ? lg[h] : NEG_SLOPE * lg[h];
                m[h] = fmaxf(m[h], lg[h]);
            }
            *(float4*)&s_lg[w][i][0] = make_float4(lg[0], lg[1], lg[2], lg[3]);
        }
        #pragma unroll
        for (int off = 16; off; off >>= 1)
            #pragma unroll
            for (int h = 0; h < 4; h++)
                m[h] = fmaxf(m[h], __shfl_xor_sync(0xffffffffu, m[h], off));

        float s[4] = {0.f, 0.f, 0.f, 0.f};
        for (int i = lane; i < tot; i += 32) {
            float4 L = *(const float4*)&s_lg[w][i][0];
            float e0 = __expf(L.x - m[0]);
            float e1 = __expf(L.y - m[1]);
            float e2 = __expf(L.z - m[2]);
            float e3 = __expf(L.w - m[3]);
            s[0] += e0; s[1] += e1; s[2] += e2; s[3] += e3;
            *(float4*)&s_lg[w][i][0] = make_float4(e0, e1, e2, e3);
        }
        #pragma unroll
        for (int off = 16; off; off >>= 1)
            #pragma unroll
            for (int h = 0; h < 4; h++)
                s[h] += __shfl_xor_sync(0xffffffffu, s[h], off);

        const float inv = 1.f / (s[myh] + 1e-16f);
        __syncwarp();

        int i = 0;
        for (; i + 4 <= tot; i += 4) {
            int   sA = s_src[w][i],     sB = s_src[w][i + 1];
            int   sC = s_src[w][i + 2], sD = s_src[w][i + 3];
            float aA = s_lg[w][i][myh] * inv,     aB = s_lg[w][i + 1][myh] * inv;
            float aC = s_lg[w][i + 2][myh] * inv, aD = s_lg[w][i + 3][myh] * inv;
            h8_accum(&g_hh[(size_t)sA * HC + lane * 8], aA, acc);
            h8_accum(&g_hh[(size_t)sB * HC + lane * 8], aB, acc);
            h8_accum(&g_hh[(size_t)sC * HC + lane * 8], aC, acc);
            h8_accum(&g_hh[(size_t)sD * HC + lane * 8], aD, acc);
        }
        for (; i < tot; i++) {
            int   s0 = s_src[w][i];
            float a0 = s_lg[w][i][myh] * inv;
            h8_accum(&g_hh[(size_t)s0 * HC + lane * 8], a0, acc);
        }
    } else {
        float m[4] = {-CUDART_INF_F, -CUDART_INF_F, -CUDART_INF_F, -CUDART_INF_F};
        for (int i = lane; i < tot; i += 32) {
            int src = (i < deg) ? g_csr[rs + i] : n;
            float4 a4 = *(const float4*)&g_asrc[src * HEADS];
            float lg[4] = {a4.x + ad[0], a4.y + ad[1], a4.z + ad[2], a4.w + ad[3]};
            #pragma unroll
            for (int h = 0; h < 4; h++) {
                float v = lg[h] >= 0.f ? lg[h] : NEG_SLOPE * lg[h];
                m[h] = fmaxf(m[h], v);
            }
        }
        #pragma unroll
        for (int off = 16; off; off >>= 1)
            #pragma unroll
            for (int h = 0; h < 4; h++)
                m[h] = fmaxf(m[h], __shfl_xor_sync(0xffffffffu, m[h], off));

        float s[4] = {0.f, 0.f, 0.f, 0.f};
        for (int i = lane; i < tot; i += 32) {
            int src = (i < deg) ? g_csr[rs + i] : n;
            float4 a4 = *(const float4*)&g_asrc[src * HEADS];
            float lg[4] = {a4.x + ad[0], a4.y + ad[1], a4.z + ad[2], a4.w + ad[3]};
            #pragma unroll
            for (int h = 0; h < 4; h++) {
                float v = lg[h] >= 0.f ? lg[h] : NEG_SLOPE * lg[h];
                s[h] += __expf(v - m[h]);
            }
        }
        #pragma unroll
        for (int off = 16; off; off >>= 1)
            #pragma unroll
            for (int h = 0; h < 4; h++)
                s[h] += __shfl_xor_sync(0xffffffffu, s[h], off);

        const float mh  = m[myh];
        const float inv = 1.f / (s[myh] + 1e-16f);
        const float adh = ad[myh];
        for (int i = 0; i < tot; i++) {
            int src = (i < deg) ? g_csr[rs + i] : n;
            float av = g_asrc[src * HEADS + myh];
            float lg = av + adh;
            lg = lg >= 0.f ? lg : NEG_SLOPE * lg;
            float alpha = __expf(lg - mh) * inv;
            h8_accum(&g_hh[(size_t)src * HC + lane * 8], alpha, acc);
        }
    }

    float4 b0 = ((const float4*)bias)[lane * 2];
    float4 b1 = ((const float4*)bias)[lane * 2 + 1];
    float4 o0, o1;
    o0.x = fmaxf(acc[0] + b0.x, 0.f); o0.y = fmaxf(acc[1] + b0.y, 0.f);
    o0.z = fmaxf(acc[2] + b0.z, 0.f); o0.w = fmaxf(acc[3] + b0.w, 0.f);
    o1.x = fmaxf(acc[4] + b1.x, 0.f); o1.y = fmaxf(acc[5] + b1.y, 0.f);
    o1.z = fmaxf(acc[6] + b1.z, 0.f); o1.w = fmaxf(acc[7] + b1.w, 0.f);
    *(float4*)&out[(size_t)n * HC + lane * 8]     = o0;
    *(float4*)&out[(size_t)n * HC + lane * 8 + 4] = o1;
}

// ---------------- launch ----------------
extern "C" void kernel_launch(void* const* d_in, const int* in_sizes, int n_in,
                              void* d_out, int out_size) {
    const float* x       = (const float*)d_in[0];
    const void*  ei      = d_in[1];
    const float* W       = (const float*)d_in[2];
    const float* att_src = (const float*)d_in[3];
    const float* att_dst = (const float*)d_in[4];
    const float* bias    = (const float*)d_in[5];
    float*       out     = (float*)d_out;

    cudaFuncSetAttribute(hgemm_kernel,
                         cudaFuncAttributeMaxDynamicSharedMemorySize, GEMM_SMEM);

    // fork
    cudaEventRecord(g_si.e1, 0);
    cudaStreamWaitEvent(g_si.s2, g_si.e1, 0);

    // side stream: W transpose first (GEMM waits on e3), then CSR build chain
    dim3 tg(8, 8);
    transpose_w_kernel<<<tg, dim3(32, 8), 0, g_si.s2>>>(W);
    cudaEventRecord(g_si.e3, g_si.s2);
    zero_deg_detect_kernel<<<(N_NODES + 255) / 256, 256, 0, g_si.s2>>>((const unsigned int*)ei);
    hist_kernel<<<(E_EDGES / 4 + 255) / 256, 256, 0, g_si.s2>>>(ei);
    scan_fused_kernel<<<NSCAN, SCAN_BLK, 0, g_si.s2>>>();
    fill_kernel<<<(E_EDGES / 4 + 255) / 256, 256, 0, g_si.s2>>>(ei);
    cudaEventRecord(g_si.e2, g_si.s2);

    // main stream: GEMM directly on fp32 x (waits on transpose)
    cudaStreamWaitEvent(0, g_si.e3, 0);
    dim3 gg(HC / GBN, (N_NODES + GBM - 1) / GBM);   // (2, 391)
    hgemm_kernel<<<gg, 256, GEMM_SMEM>>>(x, att_src, att_dst);

    // join: gather needs both chains
    cudaStreamWaitEvent(0, g_si.e2, 0);
    gat_node_kernel<<<(N_NODES + 7) / 8, 256>>>(bias, out);
}